// round 1
// baseline (speedup 1.0000x reference)
#include <cuda_runtime.h>
#include <math.h>

// Problem constants (fixed-shape instance)
#define BB 1024
#define SS 512
#define DD 768
#define FF (3*DD)   // 2304
#define H1 256
#define H2 64
#define NC 4
#define BT 8        // batch rows per MLP CTA -> 128 CTAs

// Scratch for feat = [e1 | e2 | cls], 1024 x 2304 fp32 (9.4 MB)
__device__ float g_feat[BB * FF];

// ---------------------------------------------------------------------------
// Kernel 1: span means + cls extract. One CTA per batch element, 192 threads,
// each thread owns one float4 (4 of 768 dims). Union-walk decomposed into
// disjoint contiguous ranges so every inner loop is branch-free + unrollable.
// ---------------------------------------------------------------------------
__global__ __launch_bounds__(192) void feat_kernel(
    const float* __restrict__ x,
    const int* __restrict__ e1,
    const int* __restrict__ e2)
{
    const int b = blockIdx.x;
    const int t = threadIdx.x;          // 0..191, float4 lane

    int lo1 = e1[2*b]; int hi1 = max(e1[2*b+1], lo1 + 1);
    int lo2 = e2[2*b]; int hi2 = max(e2[2*b+1], lo2 + 1);

    const float4* __restrict__ xb =
        reinterpret_cast<const float4*>(x) + (size_t)b * (SS * (DD/4));

    float4 s1 = make_float4(0.f,0.f,0.f,0.f);
    float4 s2 = make_float4(0.f,0.f,0.f,0.f);

    // range-sum helper: accumulates rows [a,c) into acc
    auto rsum = [&](int a, int c, float4& acc) {
        #pragma unroll 4
        for (int s = a; s < c; ++s) {
            float4 v = __ldcs(&xb[(size_t)s * (DD/4) + t]);
            acc.x += v.x; acc.y += v.y; acc.z += v.z; acc.w += v.w;
        }
    };

    const int mlo = max(lo1, lo2);
    const int mhi = min(hi1, hi2);
    if (mlo < mhi) {
        // overlapping spans: read overlap once
        float4 ov = make_float4(0.f,0.f,0.f,0.f);
        rsum(mlo, mhi, ov);
        rsum(lo1, mlo, s1); rsum(mhi, hi1, s1);
        rsum(lo2, mlo, s2); rsum(mhi, hi2, s2);
        s1.x += ov.x; s1.y += ov.y; s1.z += ov.z; s1.w += ov.w;
        s2.x += ov.x; s2.y += ov.y; s2.z += ov.z; s2.w += ov.w;
    } else {
        rsum(lo1, hi1, s1);
        rsum(lo2, hi2, s2);
    }

    float4 cls = xb[t];   // row s = 0 (never inside a span: spans start >= 1)

    const float r1 = 1.f / (float)(hi1 - lo1);
    const float r2 = 1.f / (float)(hi2 - lo2);

    float4* __restrict__ fb =
        reinterpret_cast<float4*>(g_feat + (size_t)b * FF);
    fb[t]           = make_float4(s1.x*r1, s1.y*r1, s1.z*r1, s1.w*r1);
    fb[(DD/4)   + t]= make_float4(s2.x*r2, s2.y*r2, s2.z*r2, s2.w*r2);
    fb[2*(DD/4) + t]= cls;
}

// ---------------------------------------------------------------------------
// Kernel 2: fused 3-layer MLP + softmax. 128 CTAs x 256 threads, BT=8 batch
// rows per CTA so W1 (2.36 MB, L2-resident) is read once per 8 rows.
// feat tile lives in dynamic smem (72 KB); all smem reads in the GEMV loops
// are warp-uniform broadcasts (conflict-free).
// ---------------------------------------------------------------------------
__global__ __launch_bounds__(256) void mlp_kernel(
    const float* __restrict__ W1, const float* __restrict__ b1,
    const float* __restrict__ W2, const float* __restrict__ b2,
    const float* __restrict__ W3, const float* __restrict__ b3,
    float* __restrict__ out)
{
    extern __shared__ float fs[];               // [BT][FF]  = 73728 B
    __shared__ float h1s[BT][H1];               // 8 KB
    __shared__ float h2s[BT][H2];               // 2 KB

    const int b0  = blockIdx.x * BT;
    const int tid = threadIdx.x;

    // --- load feat tile (coalesced float4 copy) ---
    {
        const float4* __restrict__ src =
            reinterpret_cast<const float4*>(g_feat + (size_t)b0 * FF);
        float4* __restrict__ dst = reinterpret_cast<float4*>(fs);
        #pragma unroll 4
        for (int i = tid; i < BT*FF/4; i += 256) dst[i] = src[i];
    }
    __syncthreads();

    // --- layer 1: [BT,2304] @ [2304,256], thread tid owns output column tid ---
    {
        float acc[BT];
        #pragma unroll
        for (int i = 0; i < BT; ++i) acc[i] = 0.f;

        for (int k = 0; k < FF; k += 4) {
            const float w0 = W1[(k+0)*H1 + tid];
            const float w1 = W1[(k+1)*H1 + tid];
            const float w2 = W1[(k+2)*H1 + tid];
            const float w3 = W1[(k+3)*H1 + tid];
            #pragma unroll
            for (int i = 0; i < BT; ++i) {
                float4 f = *reinterpret_cast<const float4*>(&fs[i*FF + k]);
                acc[i] = fmaf(f.x, w0, acc[i]);
                acc[i] = fmaf(f.y, w1, acc[i]);
                acc[i] = fmaf(f.z, w2, acc[i]);
                acc[i] = fmaf(f.w, w3, acc[i]);
            }
        }
        const float bb = b1[tid];
        #pragma unroll
        for (int i = 0; i < BT; ++i)
            h1s[i][tid] = fmaxf(acc[i] + bb, 0.f);
    }
    __syncthreads();

    // --- layer 2: [BT,256] @ [256,64]; thread -> (j = tid&63, rows 2*(tid>>6)+{0,1}) ---
    {
        const int j  = tid & 63;
        const int i0 = (tid >> 6) * 2;
        float a0 = 0.f, a1 = 0.f;
        #pragma unroll 4
        for (int k = 0; k < H1; ++k) {
            const float w = W2[k*H2 + j];
            a0 = fmaf(h1s[i0+0][k], w, a0);
            a1 = fmaf(h1s[i0+1][k], w, a1);
        }
        const float bb = b2[j];
        h2s[i0+0][j] = fmaxf(a0 + bb, 0.f);
        h2s[i0+1][j] = fmaxf(a1 + bb, 0.f);
    }
    __syncthreads();

    // --- layer 3 + softmax: one thread per batch row ---
    if (tid < BT) {
        const int i = tid;
        float l0 = b3[0], l1 = b3[1], l2 = b3[2], l3 = b3[3];
        #pragma unroll 8
        for (int k = 0; k < H2; ++k) {
            const float h = h2s[i][k];
            l0 = fmaf(h, W3[k*NC+0], l0);
            l1 = fmaf(h, W3[k*NC+1], l1);
            l2 = fmaf(h, W3[k*NC+2], l2);
            l3 = fmaf(h, W3[k*NC+3], l3);
        }
        float m = fmaxf(fmaxf(l0,l1), fmaxf(l2,l3));
        float e0 = expf(l0 - m), e1x = expf(l1 - m),
              e2x = expf(l2 - m), e3 = expf(l3 - m);
        float inv = 1.f / (e0 + e1x + e2x + e3);
        float* o = out + (size_t)(b0 + i) * NC;
        o[0] = e0*inv; o[1] = e1x*inv; o[2] = e2x*inv; o[3] = e3*inv;
    }
}

// ---------------------------------------------------------------------------
extern "C" void kernel_launch(void* const* d_in, const int* in_sizes, int n_in,
                              void* d_out, int out_size)
{
    const float* x   = (const float*)d_in[0];
    const int*   e1  = (const int*)  d_in[1];
    const int*   e2  = (const int*)  d_in[2];
    const float* W1  = (const float*)d_in[3];
    const float* b1  = (const float*)d_in[4];
    const float* W2  = (const float*)d_in[5];
    const float* b2  = (const float*)d_in[6];
    const float* W3  = (const float*)d_in[7];
    const float* b3  = (const float*)d_in[8];
    float* out = (float*)d_out;

    static int smem_set = 0;
    const int smem_bytes = BT * FF * (int)sizeof(float);  // 73728
    if (!smem_set) {
        cudaFuncSetAttribute(mlp_kernel,
            cudaFuncAttributeMaxDynamicSharedMemorySize, smem_bytes);
        smem_set = 1;
    }

    feat_kernel<<<BB, 192>>>(x, e1, e2);
    mlp_kernel<<<BB/BT, 256, smem_bytes>>>(W1, b1, W2, b2, W3, b3, out);
}

// round 2
// speedup vs baseline: 1.2154x; 1.2154x over previous
#include <cuda_runtime.h>
#include <math.h>

// Problem constants (fixed-shape instance)
#define BB 1024
#define SS 512
#define DD 768
#define FF (3*DD)   // 2304
#define H1 256
#define H2 64
#define NC 4
#define BT 8        // batch rows per MLP CTA -> 128 CTAs
#define KT 32       // k-tile (rows of W1 staged per cp.async stage)
#define NTILE (FF/KT)  // 72

// Scratch for feat = [e1 | e2 | cls], 1024 x 2304 fp32 (9.4 MB)
__device__ float g_feat[BB * FF];

// ---------------------------------------------------------------------------
// cp.async helpers (LDGSTS)
// ---------------------------------------------------------------------------
__device__ __forceinline__ void cp_async16(float* smem_dst, const float* gmem_src) {
    unsigned s = (unsigned)__cvta_generic_to_shared(smem_dst);
    asm volatile("cp.async.cg.shared.global [%0], [%1], 16;\n" :: "r"(s), "l"(gmem_src));
}
__device__ __forceinline__ void cp_commit() {
    asm volatile("cp.async.commit_group;\n" ::: "memory");
}
template<int N>
__device__ __forceinline__ void cp_wait() {
    asm volatile("cp.async.wait_group %0;\n" :: "n"(N) : "memory");
}

// ---------------------------------------------------------------------------
// Kernel 1: span means + cls extract. One CTA per batch element, 192 threads,
// each thread owns one float4 (4 of 768 dims). Union-walk decomposed into
// disjoint contiguous ranges so every inner loop is branch-free + unrollable.
// HBM-bound: ~855 MB effective read.
// ---------------------------------------------------------------------------
__global__ __launch_bounds__(192) void feat_kernel(
    const float* __restrict__ x,
    const int* __restrict__ e1,
    const int* __restrict__ e2)
{
    const int b = blockIdx.x;
    const int t = threadIdx.x;          // 0..191, float4 lane

    int lo1 = e1[2*b]; int hi1 = max(e1[2*b+1], lo1 + 1);
    int lo2 = e2[2*b]; int hi2 = max(e2[2*b+1], lo2 + 1);

    const float4* __restrict__ xb =
        reinterpret_cast<const float4*>(x) + (size_t)b * (SS * (DD/4));

    float4 s1 = make_float4(0.f,0.f,0.f,0.f);
    float4 s2 = make_float4(0.f,0.f,0.f,0.f);

    auto rsum = [&](int a, int c, float4& acc) {
        #pragma unroll 4
        for (int s = a; s < c; ++s) {
            float4 v = __ldcs(&xb[(size_t)s * (DD/4) + t]);
            acc.x += v.x; acc.y += v.y; acc.z += v.z; acc.w += v.w;
        }
    };

    const int mlo = max(lo1, lo2);
    const int mhi = min(hi1, hi2);
    if (mlo < mhi) {
        float4 ov = make_float4(0.f,0.f,0.f,0.f);
        rsum(mlo, mhi, ov);
        rsum(lo1, mlo, s1); rsum(mhi, hi1, s1);
        rsum(lo2, mlo, s2); rsum(mhi, hi2, s2);
        s1.x += ov.x; s1.y += ov.y; s1.z += ov.z; s1.w += ov.w;
        s2.x += ov.x; s2.y += ov.y; s2.z += ov.z; s2.w += ov.w;
    } else {
        rsum(lo1, hi1, s1);
        rsum(lo2, hi2, s2);
    }

    float4 cls = xb[t];   // row 0 (spans start >= 1)

    const float r1 = 1.f / (float)(hi1 - lo1);
    const float r2 = 1.f / (float)(hi2 - lo2);

    float4* __restrict__ fb =
        reinterpret_cast<float4*>(g_feat + (size_t)b * FF);
    fb[t]            = make_float4(s1.x*r1, s1.y*r1, s1.z*r1, s1.w*r1);
    fb[(DD/4)   + t] = make_float4(s2.x*r2, s2.y*r2, s2.z*r2, s2.w*r2);
    fb[2*(DD/4) + t] = cls;
}

// ---------------------------------------------------------------------------
// Kernel 2: fused 3-layer MLP + softmax. 128 CTAs x 256 threads, BT=8.
// Layer 1 streams W1 through smem in double-buffered KT=32 tiles via cp.async
// so the L2 latency that killed R1 is hidden asynchronously. All smem reads
// in the FMA loop are conflict-free (W1: lane-consecutive; feat: broadcast).
//
// Dynamic smem layout:
//   fs    [BT*FF]        feat tile           73728 B
//   wbuf  [2][KT*H1]     W1 double buffer    65536 B
// ---------------------------------------------------------------------------
__global__ __launch_bounds__(256) void mlp_kernel(
    const float* __restrict__ W1, const float* __restrict__ b1,
    const float* __restrict__ W2, const float* __restrict__ b2,
    const float* __restrict__ W3, const float* __restrict__ b3,
    float* __restrict__ out)
{
    extern __shared__ float fs[];               // [BT][FF]
    float* wbuf = fs + BT*FF;                   // [2][KT*H1]
    __shared__ float h1s[BT][H1];               // 8 KB
    __shared__ float h2s[BT][H2];               // 2 KB

    const int b0  = blockIdx.x * BT;
    const int tid = threadIdx.x;

    // --- start W1 tile 0 prefetch immediately ---
    {
        const float* src = W1;                  // tile 0
        #pragma unroll
        for (int i = 0; i < KT*H1/4/256; ++i)   // 8 float4 per thread
            cp_async16(wbuf + (tid + i*256)*4, src + (tid + i*256)*4);
        cp_commit();
    }

    // --- load feat tile (coalesced float4 copy), overlaps with tile-0 fetch ---
    {
        const float4* __restrict__ src =
            reinterpret_cast<const float4*>(g_feat + (size_t)b0 * FF);
        float4* __restrict__ dst = reinterpret_cast<float4*>(fs);
        #pragma unroll 4
        for (int i = tid; i < BT*FF/4; i += 256) dst[i] = src[i];
    }

    // --- layer 1: [BT,2304] @ [2304,256]; thread tid owns output column tid ---
    {
        float acc[BT];
        #pragma unroll
        for (int i = 0; i < BT; ++i) acc[i] = 0.f;

        for (int t = 0; t < NTILE; ++t) {
            if (t + 1 < NTILE) {
                const float* src = W1 + (size_t)(t+1)*KT*H1;
                float* dst = wbuf + ((t+1)&1)*KT*H1;
                #pragma unroll
                for (int i = 0; i < KT*H1/4/256; ++i)
                    cp_async16(dst + (tid + i*256)*4, src + (tid + i*256)*4);
                cp_commit();
                cp_wait<1>();       // tile t complete
            } else {
                cp_wait<0>();
            }
            __syncthreads();

            const float* ws = wbuf + (t&1)*KT*H1;
            const int kbase = t*KT;
            #pragma unroll
            for (int kk = 0; kk < KT; kk += 4) {
                const float w0 = ws[(kk+0)*H1 + tid];
                const float w1 = ws[(kk+1)*H1 + tid];
                const float w2 = ws[(kk+2)*H1 + tid];
                const float w3 = ws[(kk+3)*H1 + tid];
                #pragma unroll
                for (int i = 0; i < BT; ++i) {
                    float4 f = *reinterpret_cast<const float4*>(&fs[i*FF + kbase + kk]);
                    acc[i] = fmaf(f.x, w0, acc[i]);
                    acc[i] = fmaf(f.y, w1, acc[i]);
                    acc[i] = fmaf(f.z, w2, acc[i]);
                    acc[i] = fmaf(f.w, w3, acc[i]);
                }
            }
            __syncthreads();
        }
        const float bb = b1[tid];
        #pragma unroll
        for (int i = 0; i < BT; ++i)
            h1s[i][tid] = fmaxf(acc[i] + bb, 0.f);
    }
    __syncthreads();

    // --- layer 2: [BT,256] @ [256,64]; thread -> (j = tid&63, rows 2*(tid>>6)+{0,1}) ---
    {
        const int j  = tid & 63;
        const int i0 = (tid >> 6) * 2;
        float a0 = 0.f, a1 = 0.f;
        #pragma unroll 4
        for (int k = 0; k < H1; ++k) {
            const float w = W2[k*H2 + j];
            a0 = fmaf(h1s[i0+0][k], w, a0);
            a1 = fmaf(h1s[i0+1][k], w, a1);
        }
        const float bb = b2[j];
        h2s[i0+0][j] = fmaxf(a0 + bb, 0.f);
        h2s[i0+1][j] = fmaxf(a1 + bb, 0.f);
    }
    __syncthreads();

    // --- layer 3 + softmax: one thread per batch row ---
    if (tid < BT) {
        const int i = tid;
        float l0 = b3[0], l1 = b3[1], l2 = b3[2], l3 = b3[3];
        #pragma unroll 8
        for (int k = 0; k < H2; ++k) {
            const float h = h2s[i][k];
            l0 = fmaf(h, W3[k*NC+0], l0);
            l1 = fmaf(h, W3[k*NC+1], l1);
            l2 = fmaf(h, W3[k*NC+2], l2);
            l3 = fmaf(h, W3[k*NC+3], l3);
        }
        float m = fmaxf(fmaxf(l0,l1), fmaxf(l2,l3));
        float e0 = expf(l0 - m), e1x = expf(l1 - m),
              e2x = expf(l2 - m), e3 = expf(l3 - m);
        float inv = 1.f / (e0 + e1x + e2x + e3);
        float* o = out + (size_t)(b0 + i) * NC;
        o[0] = e0*inv; o[1] = e1x*inv; o[2] = e2x*inv; o[3] = e3*inv;
    }
}

// ---------------------------------------------------------------------------
extern "C" void kernel_launch(void* const* d_in, const int* in_sizes, int n_in,
                              void* d_out, int out_size)
{
    const float* x   = (const float*)d_in[0];
    const int*   e1  = (const int*)  d_in[1];
    const int*   e2  = (const int*)  d_in[2];
    const float* W1  = (const float*)d_in[3];
    const float* b1  = (const float*)d_in[4];
    const float* W2  = (const float*)d_in[5];
    const float* b2  = (const float*)d_in[6];
    const float* W3  = (const float*)d_in[7];
    const float* b3  = (const float*)d_in[8];
    float* out = (float*)d_out;

    static int smem_set = 0;
    const int smem_bytes = (BT*FF + 2*KT*H1) * (int)sizeof(float);  // 139264
    if (!smem_set) {
        cudaFuncSetAttribute(mlp_kernel,
            cudaFuncAttributeMaxDynamicSharedMemorySize, smem_bytes);
        smem_set = 1;
    }

    feat_kernel<<<BB, 192>>>(x, e1, e2);
    mlp_kernel<<<BB/BT, 256, smem_bytes>>>(W1, b1, W2, b2, W3, b3, out);
}